// round 7
// baseline (speedup 1.0000x reference)
#include <cuda_runtime.h>
#include <math.h>

#define BB 8
#define SS 256
#define DD 512
#define NNODE 64
#define VV 32000

// ---------------- scratch (device globals: allocation-free) ----------------
__device__ float g_xg[BB * SS * DD];          // x @ WgX + bg   (4 MB)
__device__ float g_xu[BB * SS * DD];          // x @ WuX + bu   (4 MB)
__device__ float g_H[2][BB * NNODE * DD];     // node state, double buffered (2 MB)
__device__ float g_cons[BB * SS * DD];        // consensus per (b,t)  (4 MB)
__device__ float g_cln[BB * SS * DD];         // layernormed consensus (4 MB)

// ---------------- init node state: broadcast manifold_nodes over batch ------
__global__ void init_H_kernel(const float* __restrict__ nodes) {
    int t = blockIdx.x * blockDim.x + threadIdx.x;
    const int total = BB * NNODE * DD;
    for (int i = t; i < total; i += gridDim.x * blockDim.x)
        g_H[0][i] = nodes[i % (NNODE * DD)];
}

// ---------------- embed gather + X-projection (runs once) ------------------
// grid: (16 dim-slices, 32 m-tiles), 128 threads.
// CTA computes, for 64 rows m (tokens) and 32 dims d: xg[m][d], xu[m][d].
__global__ __launch_bounds__(128) void embed_proj_kernel(
    const int* __restrict__ idx, const float* __restrict__ emb,
    const float* __restrict__ Wg, const float* __restrict__ bg,
    const float* __restrict__ Wu, const float* __restrict__ bu)
{
    const int d0 = blockIdx.x * 32;
    const int m0 = blockIdx.y * 64;
    const int tid = threadIdx.x;
    __shared__ int   idxs[64];
    __shared__ float As[64][36];   // token embeddings [row][k]
    __shared__ float Ws[32][68];   // cols 0-31: Wg slice, 32-63: Wu slice

    if (tid < 64) idxs[tid] = idx[m0 + tid];
    __syncthreads();

    const int tm = tid >> 4;       // 0..7
    const int tn = tid & 15;       // 0..15
    float acc[8][4];
#pragma unroll
    for (int i = 0; i < 8; i++)
#pragma unroll
        for (int j = 0; j < 4; j++) acc[i][j] = 0.f;

    for (int k0 = 0; k0 < DD; k0 += 32) {
#pragma unroll
        for (int i = 0; i < 4; i++) {
            int s = tid + i * 128; int n = s >> 3; int j4 = s & 7;
            float4 v = *(const float4*)(emb + (size_t)idxs[n] * DD + k0 + 4 * j4);
            *(float4*)&As[n][4 * j4] = v;
        }
#pragma unroll
        for (int i = 0; i < 2; i++) {
            int s = tid + i * 128; int kk = s >> 3; int j4 = s & 7;
            *(float4*)&Ws[kk][4 * j4]      = *(const float4*)(Wg + (size_t)(k0 + kk) * DD + d0 + 4 * j4);
            *(float4*)&Ws[kk][32 + 4 * j4] = *(const float4*)(Wu + (size_t)(k0 + kk) * DD + d0 + 4 * j4);
        }
        __syncthreads();
#pragma unroll
        for (int kk = 0; kk < 32; kk++) {
            float w[4]; *(float4*)w = *(float4*)&Ws[kk][4 * tn];
            float a[8];
#pragma unroll
            for (int i = 0; i < 8; i++) a[i] = As[tm + 8 * i][kk];
#pragma unroll
            for (int i = 0; i < 8; i++)
#pragma unroll
                for (int j = 0; j < 4; j++) acc[i][j] += a[i] * w[j];
        }
        __syncthreads();
    }

    if (tn < 8) {
#pragma unroll
        for (int i = 0; i < 8; i++) {
            int m = m0 + tm + 8 * i;
#pragma unroll
            for (int j = 0; j < 4; j++) {
                int c = d0 + 4 * tn + j;
                g_xg[(size_t)m * DD + c] = acc[i][j] + bg[c];
            }
        }
    } else {
#pragma unroll
        for (int i = 0; i < 8; i++) {
            int m = m0 + tm + 8 * i;
#pragma unroll
            for (int j = 0; j < 4; j++) {
                int c = d0 + 4 * (tn - 8) + j;
                g_xu[(size_t)m * DD + c] = acc[i][j] + bu[c];
            }
        }
    }
}

// ---------------- one recurrence step ---------------------------------------
// grid: (16 dim-slices, 8 batches), 128 threads.
// CTA: G/U = H_b[64,512] @ {Wg,Wu}_H[:, d0:d0+32]; gate update; consensus slice.
__global__ __launch_bounds__(128) void step_kernel(
    const float* __restrict__ Wg, const float* __restrict__ Wu,
    int t, int par)
{
    const int d0 = blockIdx.x * 32;
    const int b  = blockIdx.y;
    const int tid = threadIdx.x;
    const float* Hin  = g_H[par]     + (size_t)b * NNODE * DD;
    float*       Hout = g_H[par ^ 1] + (size_t)b * NNODE * DD;

    __shared__ float As[64][36];     // H rows [node][k-chunk]
    __shared__ float Ws[32][68];     // [k][0-31 g | 32-63 u]
    __shared__ float outS[64][68];   // GEMM result [node][0-31 g | 32-63 u]
    __shared__ float cpart[4][32];

    const int tm = tid >> 4;         // 0..7
    const int tn = tid & 15;         // 0..15
    float acc[8][4];
#pragma unroll
    for (int i = 0; i < 8; i++)
#pragma unroll
        for (int j = 0; j < 4; j++) acc[i][j] = 0.f;

    float4 pa[4], pg[2], pu[2];
    // prefetch chunk k0 = 0
#pragma unroll
    for (int i = 0; i < 4; i++) {
        int s = tid + i * 128; int n = s >> 3; int j4 = s & 7;
        pa[i] = *(const float4*)(Hin + n * DD + 4 * j4);
    }
#pragma unroll
    for (int i = 0; i < 2; i++) {
        int s = tid + i * 128; int kk = s >> 3; int j4 = s & 7;
        pg[i] = *(const float4*)(Wg + (size_t)(DD + kk) * DD + d0 + 4 * j4);
        pu[i] = *(const float4*)(Wu + (size_t)(DD + kk) * DD + d0 + 4 * j4);
    }

    for (int k0 = 0; k0 < DD; k0 += 32) {
#pragma unroll
        for (int i = 0; i < 4; i++) {
            int s = tid + i * 128; int n = s >> 3; int j4 = s & 7;
            *(float4*)&As[n][4 * j4] = pa[i];
        }
#pragma unroll
        for (int i = 0; i < 2; i++) {
            int s = tid + i * 128; int kk = s >> 3; int j4 = s & 7;
            *(float4*)&Ws[kk][4 * j4]      = pg[i];
            *(float4*)&Ws[kk][32 + 4 * j4] = pu[i];
        }
        __syncthreads();

        const int k1 = k0 + 32;
        if (k1 < DD) {
#pragma unroll
            for (int i = 0; i < 4; i++) {
                int s = tid + i * 128; int n = s >> 3; int j4 = s & 7;
                pa[i] = *(const float4*)(Hin + n * DD + k1 + 4 * j4);
            }
#pragma unroll
            for (int i = 0; i < 2; i++) {
                int s = tid + i * 128; int kk = s >> 3; int j4 = s & 7;
                pg[i] = *(const float4*)(Wg + (size_t)(DD + k1 + kk) * DD + d0 + 4 * j4);
                pu[i] = *(const float4*)(Wu + (size_t)(DD + k1 + kk) * DD + d0 + 4 * j4);
            }
        }

#pragma unroll
        for (int kk = 0; kk < 32; kk++) {
            float w[4]; *(float4*)w = *(float4*)&Ws[kk][4 * tn];
            float a[8];
#pragma unroll
            for (int i = 0; i < 8; i++) a[i] = As[tm + 8 * i][kk];
#pragma unroll
            for (int i = 0; i < 8; i++)
#pragma unroll
                for (int j = 0; j < 4; j++) acc[i][j] += a[i] * w[j];
        }
        __syncthreads();
    }

    // stash GEMM results, then recombine g/c per (node, dim)
#pragma unroll
    for (int i = 0; i < 8; i++)
#pragma unroll
        for (int j = 0; j < 4; j++) outS[tm + 8 * i][4 * tn + j] = acc[i][j];
    __syncthreads();

    const int d  = tid & 31;   // 0..31 (dim within slice)
    const int ng = tid >> 5;   // 0..3  (node group)
    const float xgv = g_xg[((size_t)b * SS + t) * DD + d0 + d];
    const float xuv = g_xu[((size_t)b * SS + t) * DD + d0 + d];
    float sum = 0.f;
#pragma unroll
    for (int q = 0; q < 16; q++) {
        int n = ng * 16 + q;
        float gp = outS[n][d]      + xgv;
        float up = outS[n][32 + d] + xuv;
        float gv = 1.f / (1.f + expf(-gp));
        float cv = tanhf(up);
        float h  = Hin[n * DD + d0 + d];
        float hn = gv * cv + (1.f - gv) * h;
        Hout[n * DD + d0 + d] = hn;
        sum += hn;
    }
    cpart[ng][d] = sum;
    __syncthreads();
    if (tid < 32) {
        float tot = cpart[0][tid] + cpart[1][tid] + cpart[2][tid] + cpart[3][tid];
        g_cons[((size_t)b * SS + t) * DD + d0 + tid] = tot * (1.0f / 64.0f);
    }
}

// ---------------- layernorm over consensus rows -----------------------------
__global__ void layernorm_kernel(const float* __restrict__ lnw,
                                 const float* __restrict__ lnb)
{
    const int r = blockIdx.x;          // 0..2047
    const int tid = threadIdx.x;       // 256
    const float* x = g_cons + (size_t)r * DD;
    float x0 = x[tid], x1 = x[tid + 256];
    __shared__ float red[256];
    red[tid] = x0 + x1;
    __syncthreads();
    for (int s = 128; s > 0; s >>= 1) {
        if (tid < s) red[tid] += red[tid + s];
        __syncthreads();
    }
    float mu = red[0] * (1.f / 512.f);
    __syncthreads();
    float dv0 = x0 - mu, dv1 = x1 - mu;
    red[tid] = dv0 * dv0 + dv1 * dv1;
    __syncthreads();
    for (int s = 128; s > 0; s >>= 1) {
        if (tid < s) red[tid] += red[tid + s];
        __syncthreads();
    }
    float var = red[0] * (1.f / 512.f);
    float rs = rsqrtf(var + 1e-5f);
    g_cln[(size_t)r * DD + tid]       = dv0 * rs * lnw[tid] + lnb[tid];
    g_cln[(size_t)r * DD + tid + 256] = dv1 * rs * lnw[tid + 256] + lnb[tid + 256];
}

// ---------------- logits GEMM: [2048,512] @ [512,32000] + bh ----------------
// grid: (500 v-tiles, 32 m-tiles), 128 threads, 64x64 tile, 8x4 microtile.
__global__ __launch_bounds__(128) void logits_kernel(
    const float* __restrict__ Wh, const float* __restrict__ bh,
    float* __restrict__ out)
{
    const int v0 = blockIdx.x * 64;
    const int m0 = blockIdx.y * 64;
    const int tid = threadIdx.x;
    __shared__ float As[64][36];
    __shared__ float Bs[32][68];
    const int tm = tid >> 4;
    const int tn = tid & 15;
    float acc[8][4];
#pragma unroll
    for (int i = 0; i < 8; i++)
#pragma unroll
        for (int j = 0; j < 4; j++) acc[i][j] = 0.f;

    float4 pa[4], pb[4];
#pragma unroll
    for (int i = 0; i < 4; i++) {
        int s = tid + i * 128; int n = s >> 3; int j4 = s & 7;
        pa[i] = *(const float4*)(g_cln + (size_t)(m0 + n) * DD + 4 * j4);
    }
#pragma unroll
    for (int i = 0; i < 4; i++) {
        int s = tid + i * 128; int kk = s >> 4; int j4 = s & 15;
        pb[i] = *(const float4*)(Wh + (size_t)kk * VV + v0 + 4 * j4);
    }

    for (int k0 = 0; k0 < DD; k0 += 32) {
#pragma unroll
        for (int i = 0; i < 4; i++) {
            int s = tid + i * 128; int n = s >> 3; int j4 = s & 7;
            *(float4*)&As[n][4 * j4] = pa[i];
        }
#pragma unroll
        for (int i = 0; i < 4; i++) {
            int s = tid + i * 128; int kk = s >> 4; int j4 = s & 15;
            *(float4*)&Bs[kk][4 * j4] = pb[i];
        }
        __syncthreads();

        const int k1 = k0 + 32;
        if (k1 < DD) {
#pragma unroll
            for (int i = 0; i < 4; i++) {
                int s = tid + i * 128; int n = s >> 3; int j4 = s & 7;
                pa[i] = *(const float4*)(g_cln + (size_t)(m0 + n) * DD + k1 + 4 * j4);
            }
#pragma unroll
            for (int i = 0; i < 4; i++) {
                int s = tid + i * 128; int kk = s >> 4; int j4 = s & 15;
                pb[i] = *(const float4*)(Wh + (size_t)(k1 + kk) * VV + v0 + 4 * j4);
            }
        }

#pragma unroll
        for (int kk = 0; kk < 32; kk++) {
            float w[4]; *(float4*)w = *(float4*)&Bs[kk][4 * tn];
            float a[8];
#pragma unroll
            for (int i = 0; i < 8; i++) a[i] = As[tm + 8 * i][kk];
#pragma unroll
            for (int i = 0; i < 8; i++)
#pragma unroll
                for (int j = 0; j < 4; j++) acc[i][j] += a[i] * w[j];
        }
        __syncthreads();
    }

    float4 bias = *(const float4*)(bh + v0 + 4 * tn);
#pragma unroll
    for (int i = 0; i < 8; i++) {
        int m = m0 + tm + 8 * i;
        float4 o;
        o.x = acc[i][0] + bias.x;
        o.y = acc[i][1] + bias.y;
        o.z = acc[i][2] + bias.z;
        o.w = acc[i][3] + bias.w;
        *(float4*)(out + (size_t)m * VV + v0 + 4 * tn) = o;
    }
}

// ---------------- launch ----------------------------------------------------
extern "C" void kernel_launch(void* const* d_in, const int* in_sizes, int n_in,
                              void* d_out, int out_size) {
    (void)in_sizes; (void)n_in; (void)out_size;
    const int*   idx   = (const int*)  d_in[0];
    const float* emb   = (const float*)d_in[1];
    const float* nodes = (const float*)d_in[2];
    const float* Wg    = (const float*)d_in[3];
    const float* bg    = (const float*)d_in[4];
    const float* Wu    = (const float*)d_in[5];
    const float* bu    = (const float*)d_in[6];
    const float* lnw   = (const float*)d_in[7];
    const float* lnb   = (const float*)d_in[8];
    const float* Wh    = (const float*)d_in[9];
    const float* bh    = (const float*)d_in[10];
    float* out = (float*)d_out;

    init_H_kernel<<<256, 256>>>(nodes);
    embed_proj_kernel<<<dim3(16, 32), 128>>>(idx, emb, Wg, bg, Wu, bu);
    for (int t = 0; t < SS; t++)
        step_kernel<<<dim3(16, 8), 128>>>(Wg, Wu, t, t & 1);
    layernorm_kernel<<<BB * SS, 256>>>(lnw, lnb);
    logits_kernel<<<dim3(VV / 64, (BB * SS) / 64), 128>>>(Wh, bh, out);
}